// round 9
// baseline (speedup 1.0000x reference)
#include <cuda_runtime.h>
#include <cuda_bf16.h>
#include <cstdint>

// ===========================================================================
// Tree-RNN round 8:
//  - leaf GEMM: 256 threads, 8 warps as 2(M)x4(N), warp tile 32x32 (halves
//    ldsm bytes/MAC vs 16x32 -> tensor-bound), BK=64, double-buffered.
//  - tree: no smem weight cache (W via __ldg, L1-resident); high-occupancy
//    cascade 512x16x4 -> 64x8x3 -> 1x64x6 + projection.
// ===========================================================================

// ----------------------------- scratch ------------------------------------
__device__ __nv_bfloat16 g_Bhi[128 * 4096];
__device__ __nv_bfloat16 g_Blo[128 * 4096];
__device__ float g_WTt[200 * 100];           // W k-major: WTt[k*100+n]
__device__ float g_h0[8192 * 100];
__device__ float g_t1[512 * 100];
__device__ float g_t2[64 * 100];

// ----------------------------- helpers ------------------------------------
__device__ __forceinline__ void cp16(uint32_t saddr, const void* g) {
    asm volatile("cp.async.cg.shared.global [%0], [%1], 16;" :: "r"(saddr), "l"(g));
}
__device__ __forceinline__ void cp_commit() { asm volatile("cp.async.commit_group;"); }
__device__ __forceinline__ void cp_wait0()  { asm volatile("cp.async.wait_group 0;"); }

__device__ __forceinline__ void ldsm_x4(uint32_t& r0, uint32_t& r1, uint32_t& r2,
                                        uint32_t& r3, uint32_t addr) {
    asm volatile("ldmatrix.sync.aligned.m8n8.x4.shared.b16 {%0,%1,%2,%3}, [%4];"
                 : "=r"(r0), "=r"(r1), "=r"(r2), "=r"(r3) : "r"(addr));
}
__device__ __forceinline__ void mma16816(float* c, const uint32_t* a, const uint32_t* b) {
    asm volatile(
        "mma.sync.aligned.m16n8k16.row.col.f32.bf16.bf16.f32 "
        "{%0,%1,%2,%3}, {%4,%5,%6,%7}, {%8,%9}, {%0,%1,%2,%3};"
        : "+f"(c[0]), "+f"(c[1]), "+f"(c[2]), "+f"(c[3])
        : "r"(a[0]), "r"(a[1]), "r"(a[2]), "r"(a[3]), "r"(b[0]), "r"(b[1]));
}

__device__ __forceinline__ void split8(float4 a, float4 b, uint4& hv, uint4& lv) {
    __nv_bfloat162 h0 = __float22bfloat162_rn(make_float2(a.x, a.y));
    __nv_bfloat162 h1 = __float22bfloat162_rn(make_float2(a.z, a.w));
    __nv_bfloat162 h2 = __float22bfloat162_rn(make_float2(b.x, b.y));
    __nv_bfloat162 h3 = __float22bfloat162_rn(make_float2(b.z, b.w));
    float2 f0 = __bfloat1622float2(h0), f1 = __bfloat1622float2(h1);
    float2 f2 = __bfloat1622float2(h2), f3 = __bfloat1622float2(h3);
    __nv_bfloat162 l0 = __float22bfloat162_rn(make_float2(a.x - f0.x, a.y - f0.y));
    __nv_bfloat162 l1 = __float22bfloat162_rn(make_float2(a.z - f1.x, a.w - f1.y));
    __nv_bfloat162 l2 = __float22bfloat162_rn(make_float2(b.x - f2.x, b.y - f2.y));
    __nv_bfloat162 l3 = __float22bfloat162_rn(make_float2(b.z - f3.x, b.w - f3.y));
    hv = make_uint4(*(uint32_t*)&h0, *(uint32_t*)&h1, *(uint32_t*)&h2, *(uint32_t*)&h3);
    lv = make_uint4(*(uint32_t*)&l0, *(uint32_t*)&l1, *(uint32_t*)&l2, *(uint32_t*)&l3);
}

// ----------------------------- prep kernels --------------------------------
__global__ void prep_B(const float* __restrict__ We,
                       __nv_bfloat16* __restrict__ bhi, __nv_bfloat16* __restrict__ blo) {
    int idx = blockIdx.x * blockDim.x + threadIdx.x;
    if (idx >= 128 * 4096) return;
    int n = idx >> 12;
    float v = (n < 100) ? We[idx] : 0.0f;
    __nv_bfloat16 h = __float2bfloat16(v);
    bhi[idx] = h;
    blo[idx] = __float2bfloat16(v - __bfloat162float(h));
}
__global__ void prep_WTt(const float* __restrict__ W, float* __restrict__ dst) {
    int idx = blockIdx.x * blockDim.x + threadIdx.x;
    if (idx >= 200 * 100) return;
    int k = idx / 100, n = idx % 100;
    dst[idx] = W[n * 200 + k];
}

// ----------------------------- leaf GEMM -----------------------------------
// C[8192,100] = relu(A[8192,4096] @ WeT + bias)
// BM=64, BN=128, BK=64; 8 warps 2(M)x4(N), warp tile 32x32. 144B rows.
#define AROWB     144
#define S_AHI     0
#define S_ALO     (64 * AROWB)
#define S_BHI     (2 * 64 * AROWB)
#define S_BLO     (S_BHI + 128 * AROWB)
#define LSTAGE    (S_BLO + 128 * AROWB)     // 55296
#define LEAF_SMEM (2 * LSTAGE)              // 110592

__global__ __launch_bounds__(256)
void leaf_gemm_mma(const float* __restrict__ A,
                   const __nv_bfloat16* __restrict__ Bhi,
                   const __nv_bfloat16* __restrict__ Blo,
                   const float* __restrict__ bias,
                   float* __restrict__ C) {
    extern __shared__ char smem[];
    const uint32_t sbase = (uint32_t)__cvta_generic_to_shared(smem);

    const int tid  = threadIdx.x;
    const int lane = tid & 31;
    const int wid  = tid >> 5;
    const int wm   = wid >> 2;       // 0..1 (32 rows each)
    const int wn   = wid & 3;        // 0..3 (32 cols each)
    const int row0 = blockIdx.x * 64;

    const int mat = lane >> 3, r8 = lane & 7;
    uint32_t aoff[2];
#pragma unroll
    for (int mt = 0; mt < 2; mt++)
        aoff[mt] = (uint32_t)((wm * 32 + mt * 16 + (mat & 1) * 8 + r8) * AROWB +
                              (mat >> 1) * 16);
    uint32_t boff[2];
#pragma unroll
    for (int nt = 0; nt < 2; nt++)
        boff[nt] = (uint32_t)((wn * 32 + nt * 16 + (mat >> 1) * 8 + r8) * AROWB +
                              (mat & 1) * 16);

    // A loads: 64 rows x 64 k fp32 -> 16 floats/thread
    const int ar  = tid >> 2;             // 0..63
    const int aks = tid & 3;              // 0..3, 16 floats each
    const float* agp = A + (size_t)(row0 + ar) * 4096 + aks * 16;
    const uint32_t adof = (uint32_t)(ar * AROWB + aks * 32);

    const char* bhp = (const char*)Bhi;
    const char* blp = (const char*)Blo;

    float acc[2][4][4];
#pragma unroll
    for (int mt = 0; mt < 2; mt++)
#pragma unroll
        for (int j = 0; j < 4; j++)
#pragma unroll
            for (int c = 0; c < 4; c++) acc[mt][j][c] = 0.0f;

    float4 av[4];

    // ---- prologue: chunk 0 ----
    {
#pragma unroll
        for (int q = 0; q < 4; q++) {
            int idx = tid + q * 256;               // 1024 segs per tile
            int brow = idx >> 3, seg = idx & 7;
            uint32_t dof = (uint32_t)(brow * AROWB + seg * 16);
            size_t gof = (size_t)brow * 8192 + seg * 16;
            cp16(sbase + S_BHI + dof, bhp + gof);
            cp16(sbase + S_BLO + dof, blp + gof);
        }
        cp_commit();
#pragma unroll
        for (int j = 0; j < 4; j++) av[j] = *(const float4*)(agp + j * 4);
        uint4 hv, lv;
        split8(av[0], av[1], hv, lv);
        *(uint4*)(smem + S_AHI + adof) = hv;
        *(uint4*)(smem + S_ALO + adof) = lv;
        split8(av[2], av[3], hv, lv);
        *(uint4*)(smem + S_AHI + adof + 16) = hv;
        *(uint4*)(smem + S_ALO + adof + 16) = lv;
    }

    for (int i = 0; i < 64; i++) {
        const int s = i & 1;
        const uint32_t st = sbase + s * LSTAGE;
        const uint32_t nst = sbase + (s ^ 1) * LSTAGE;
        char* nst_gen = smem + (s ^ 1) * LSTAGE;

        cp_wait0();          // B chunk i resident
        __syncthreads();     // A chunk i visible; stage s^1 free

        if (i < 63) {
            const size_t kb = (size_t)(i + 1) * 128;  // bytes (64 bf16)
#pragma unroll
            for (int q = 0; q < 4; q++) {
                int idx = tid + q * 256;
                int brow = idx >> 3, seg = idx & 7;
                uint32_t dof = (uint32_t)(brow * AROWB + seg * 16);
                size_t gof = (size_t)brow * 8192 + kb + seg * 16;
                cp16(nst + S_BHI + dof, bhp + gof);
                cp16(nst + S_BLO + dof, blp + gof);
            }
            cp_commit();
            const float* ap = agp + (size_t)(i + 1) * 64;
#pragma unroll
            for (int j = 0; j < 4; j++) av[j] = *(const float4*)(ap + j * 4);
        }

        // ---- compute chunk i: 4 x k16 ----
#pragma unroll
        for (int kk = 0; kk < 4; kk++) {
            const uint32_t kb = (uint32_t)(kk * 32);
            uint32_t ah[2][4], al[2][4], bh[2][4], bl[2][4];
#pragma unroll
            for (int mt = 0; mt < 2; mt++) {
                ldsm_x4(ah[mt][0], ah[mt][1], ah[mt][2], ah[mt][3],
                        st + S_AHI + aoff[mt] + kb);
                ldsm_x4(al[mt][0], al[mt][1], al[mt][2], al[mt][3],
                        st + S_ALO + aoff[mt] + kb);
            }
#pragma unroll
            for (int nt = 0; nt < 2; nt++) {
                ldsm_x4(bh[nt][0], bh[nt][1], bh[nt][2], bh[nt][3],
                        st + S_BHI + boff[nt] + kb);
                ldsm_x4(bl[nt][0], bl[nt][1], bl[nt][2], bl[nt][3],
                        st + S_BLO + boff[nt] + kb);
            }
#pragma unroll
            for (int mt = 0; mt < 2; mt++)
#pragma unroll
                for (int j = 0; j < 4; j++) {
                    const int nt = j >> 1, p = (j & 1) * 2;
                    uint32_t bhr[2] = {bh[nt][p], bh[nt][p + 1]};
                    uint32_t blr[2] = {bl[nt][p], bl[nt][p + 1]};
                    mma16816(acc[mt][j], ah[mt], bhr);
                    mma16816(acc[mt][j], ah[mt], blr);
                    mma16816(acc[mt][j], al[mt], bhr);
                }
        }

        // ---- convert + STS A chunk i+1 into stage s^1 ----
        if (i < 63) {
            uint4 hv, lv;
            split8(av[0], av[1], hv, lv);
            *(uint4*)(nst_gen + S_AHI + adof) = hv;
            *(uint4*)(nst_gen + S_ALO + adof) = lv;
            split8(av[2], av[3], hv, lv);
            *(uint4*)(nst_gen + S_AHI + adof + 16) = hv;
            *(uint4*)(nst_gen + S_ALO + adof + 16) = lv;
        }
    }

    // ---- epilogue ----
#pragma unroll
    for (int mt = 0; mt < 2; mt++) {
        const int row = row0 + wm * 32 + mt * 16 + (lane >> 2);
#pragma unroll
        for (int j = 0; j < 4; j++) {
            const int col = wn * 32 + j * 8 + (lane & 3) * 2;
#pragma unroll
            for (int c = 0; c < 4; c++) {
                const int rr = row + (c >> 1) * 8;
                const int cc = col + (c & 1);
                if (cc < 100)
                    C[(size_t)rr * 100 + cc] =
                        fmaxf(acc[mt][j][c] + __ldg(bias + cc), 0.0f);
            }
        }
    }
}

// ----------------------------- tree cascade --------------------------------
// 128 threads/block; W via __ldg (L1-resident, shared by all blocks);
// only the activations live in smem (broadcast reads, conflict-free).
template <int ROWS_IN, int NLEV>
__device__ __forceinline__ const float* tree_body(const float* __restrict__ in_rows,
                                                  const float* __restrict__ Wt,
                                                  const float* __restrict__ b,
                                                  float* bufA, float* bufB) {
    for (int i = threadIdx.x; i < ROWS_IN * 100; i += 128) bufA[i] = in_rows[i];
    __syncthreads();

    const float* cur = bufA;
    float* nxt = bufB;
    int m = ROWS_IN;
    const int n = threadIdx.x;
    const float bn = (n < 100) ? __ldg(b + n) : 0.0f;

#pragma unroll
    for (int l = 0; l < NLEV; l++) {
        const int mo = m >> 1;
        if (n < 100) {
            for (int rg = 0; rg < mo; rg += 8) {
                const int nr = (mo - rg < 8) ? (mo - rg) : 8;
                float acc[8];
#pragma unroll
                for (int c = 0; c < 8; c++) acc[c] = 0.0f;
                for (int k0 = 0; k0 < 200; k0 += 8) {
                    float w[8];
#pragma unroll
                    for (int j = 0; j < 8; j++) w[j] = __ldg(Wt + (k0 + j) * 100 + n);
#pragma unroll
                    for (int c = 0; c < 8; c++) {
                        if (c < nr) {
                            const float* xp = cur + (rg + c) * 200 + k0;
                            float4 x0 = *(const float4*)(xp);
                            float4 x1 = *(const float4*)(xp + 4);
                            acc[c] = fmaf(x0.x, w[0], acc[c]);
                            acc[c] = fmaf(x0.y, w[1], acc[c]);
                            acc[c] = fmaf(x0.z, w[2], acc[c]);
                            acc[c] = fmaf(x0.w, w[3], acc[c]);
                            acc[c] = fmaf(x1.x, w[4], acc[c]);
                            acc[c] = fmaf(x1.y, w[5], acc[c]);
                            acc[c] = fmaf(x1.z, w[6], acc[c]);
                            acc[c] = fmaf(x1.w, w[7], acc[c]);
                        }
                    }
                }
#pragma unroll
                for (int c = 0; c < 8; c++)
                    if (c < nr) nxt[(rg + c) * 100 + n] = fmaxf(acc[c] + bn, 0.0f);
            }
        }
        __syncthreads();
        const float* t = cur; cur = nxt; nxt = (float*)t;
        m = mo;
    }
    return cur;
}

__global__ __launch_bounds__(128)
void tree_stage1(const float* __restrict__ in, float* __restrict__ out,
                 const float* __restrict__ Wt, const float* __restrict__ b) {
    extern __shared__ float sm[];
    const float* res = tree_body<16, 4>(in + (size_t)blockIdx.x * 1600, Wt, b,
                                        sm, sm + 1600);
    if (threadIdx.x < 100) out[blockIdx.x * 100 + threadIdx.x] = res[threadIdx.x];
}
__global__ __launch_bounds__(128)
void tree_stage2(const float* __restrict__ in, float* __restrict__ out,
                 const float* __restrict__ Wt, const float* __restrict__ b) {
    extern __shared__ float sm[];
    const float* res = tree_body<8, 3>(in + (size_t)blockIdx.x * 800, Wt, b,
                                       sm, sm + 800);
    if (threadIdx.x < 100) out[blockIdx.x * 100 + threadIdx.x] = res[threadIdx.x];
}
__global__ __launch_bounds__(128)
void tree_stage3(const float* __restrict__ in, float* __restrict__ out,
                 const float* __restrict__ Wt, const float* __restrict__ b,
                 const float* __restrict__ Wp, const float* __restrict__ bp) {
    extern __shared__ float sm[];
    const float* res = tree_body<64, 6>(in, Wt, b, sm, sm + 6400);
    if (threadIdx.x < 64) {
        const int c = threadIdx.x >> 5;
        const int lane = threadIdx.x & 31;
        float s = 0.0f;
        for (int k = lane; k < 100; k += 32) s += __ldg(Wp + c * 100 + k) * res[k];
#pragma unroll
        for (int o = 16; o > 0; o >>= 1) s += __shfl_down_sync(0xffffffffu, s, o);
        if (lane == 0) out[c] = s + __ldg(bp + c);
    }
}

// ------------------------------ launch -------------------------------------
extern "C" void kernel_launch(void* const* d_in, const int* in_sizes, int n_in,
                              void* d_out, int out_size) {
    const float* leaf = (const float*)d_in[0];  // [8192, 4096]
    const float* We   = (const float*)d_in[1];  // [100, 4096]
    const float* be   = (const float*)d_in[2];  // [100]
    const float* W    = (const float*)d_in[3];  // [100, 200]
    const float* b    = (const float*)d_in[4];  // [100]
    const float* Wp   = (const float*)d_in[5];  // [2, 100]
    const float* bp   = (const float*)d_in[6];  // [2]
    float* out = (float*)d_out;

    __nv_bfloat16 *Bhi, *Blo;
    float *WTt, *h0, *t1, *t2;
    cudaGetSymbolAddress((void**)&Bhi, g_Bhi);
    cudaGetSymbolAddress((void**)&Blo, g_Blo);
    cudaGetSymbolAddress((void**)&WTt, g_WTt);
    cudaGetSymbolAddress((void**)&h0, g_h0);
    cudaGetSymbolAddress((void**)&t1, g_t1);
    cudaGetSymbolAddress((void**)&t2, g_t2);

    static int attr_set = 0;
    if (!attr_set) {
        cudaFuncSetAttribute(leaf_gemm_mma, cudaFuncAttributeMaxDynamicSharedMemorySize,
                             LEAF_SMEM);
        attr_set = 1;
    }

    prep_B<<<(128 * 4096 + 255) / 256, 256>>>(We, Bhi, Blo);
    prep_WTt<<<(200 * 100 + 255) / 256, 256>>>(W, WTt);

    leaf_gemm_mma<<<128, 256, LEAF_SMEM>>>(leaf, Bhi, Blo, be, h0);

    tree_stage1<<<512, 128, (1600 + 800) * 4>>>(h0, t1, WTt, b);
    tree_stage2<<<64, 128, (800 + 400) * 4>>>(t1, t2, WTt, b);
    tree_stage3<<<1, 128, (6400 + 3200) * 4>>>(t2, out, WTt, b, Wp, bp);
}